// round 2
// baseline (speedup 1.0000x reference)
#include <cuda_runtime.h>

#define LNUM 3
#define ENUM 1000000
#define NNODE 100000
#define DDIM 64
#define ADIM 8
#define NR2C 461
#define QNUM 1000
#define ENTC 10000

// ---------------- scratch (device globals; no allocation) ----------------
__device__ float g_state[NNODE * DDIM];
__device__ float g_agg[NNODE * DDIM];
__device__ float g_X[NNODE * DDIM];
__device__ float g_GI[NNODE * 192];
__device__ float g_GH[NNODE * 192];
__device__ float g_nproj[NNODE * ADIM];
__device__ float g_rproj[NR2C * ADIM];
__device__ float g_qproj[QNUM * ADIM];
__device__ float g_bWh[LNUM * 4096];    // per-layer 8ks x 8nt x 32 x 2
__device__ float g_bWih[12288];         // 8ks x 24nt x 32 x 2
__device__ float g_bWhh[12288];
__device__ float g_scores[NNODE];
__device__ int   g_winner[QNUM * ENTC];

// ---------------- helpers ----------------
__device__ __forceinline__ unsigned f2tf(float x) {
    unsigned u;
    asm("cvt.rna.tf32.f32 %0, %1;" : "=r"(u) : "f"(x));
    return u;
}
__device__ __forceinline__ float sigf(float x) { return 1.f / (1.f + __expf(-x)); }

// ---------------- init kernels ----------------
__global__ void k_zero4(float4* p, int n) {
    int i = blockIdx.x * blockDim.x + threadIdx.x;
    if (i < n) p[i] = make_float4(0.f, 0.f, 0.f, 0.f);
}
__global__ void k_filli4(int4* p, int n, int v) {
    int i = blockIdx.x * blockDim.x + threadIdx.x;
    if (i < n) p[i] = make_int4(v, v, v, v);
}

// ---------------- B-fragment precompute (tf32, mma-swizzled) ----------------
__device__ __forceinline__ float bval(const float* W, int e, int NT) {
    int j = e & 1;
    int lane = (e >> 1) & 31;
    int nk = e >> 6;
    int ntg = nk % NT;
    int ks = nk / NT;
    int n = ntg * 8 + (lane >> 2);
    int k = ks * 8 + (lane & 3) + 4 * j;
    return __uint_as_float(f2tf(W[n * 64 + k]));
}
__global__ void k_bfrag(const float* __restrict__ Wh, const float* __restrict__ Wih,
                        const float* __restrict__ Whh) {
    int i = blockIdx.x * blockDim.x + threadIdx.x;
    const int WH = 4096, WI = 12288;
    if (i < 3 * WH) {
        int layer = i / WH, e = i % WH;
        g_bWh[i] = bval(Wh + layer * 4096, e, 8);
    } else if (i < 3 * WH + WI) {
        int e = i - 3 * WH;
        g_bWih[e] = bval(Wih, e, 24);
    } else if (i < 3 * WH + 2 * WI) {
        int e = i - 3 * WH - WI;
        g_bWhh[e] = bval(Whh, e, 24);
    }
}

// ---------------- per-layer projections: node/rel/query-rel -> 8 attn dims ----
__global__ void k_proj(const float* __restrict__ emb, const float* __restrict__ Ws,
                       const float* __restrict__ Wr, const float* __restrict__ Wqr,
                       const float* __restrict__ Wqrb, const int* __restrict__ relation) {
    int w = (blockIdx.x * blockDim.x + threadIdx.x) >> 5;
    int lane = threadIdx.x & 31;
    const int R = NNODE + NR2C + QNUM;
    if (w >= R) return;
    const float* src;
    const float* W;
    float* dst;
    bool isQ = false;
    if (w < NNODE) {
        src = g_state + (size_t)w * 64; W = Ws; dst = g_nproj + w * 8;
    } else if (w < NNODE + NR2C) {
        int r = w - NNODE;
        src = emb + (size_t)r * 64; W = Wr; dst = g_rproj + r * 8;
    } else {
        int q = w - NNODE - NR2C;
        src = emb + (size_t)relation[q] * 64; W = Wqr; dst = g_qproj + q * 8;
        isQ = true;
    }
    float2 s2 = ((const float2*)src)[lane];
    float res = 0.f;
#pragma unroll
    for (int a = 0; a < 8; a++) {
        float2 w2 = __ldg((const float2*)(W + a * 64) + lane);
        float p = s2.x * w2.x + s2.y * w2.y;
#pragma unroll
        for (int m = 16; m >= 1; m >>= 1) p += __shfl_xor_sync(0xffffffffu, p, m);
        if (lane == a) res = p;
    }
    if (lane < 8) dst[lane] = res + (isQ ? Wqrb[lane] : 0.f);
}

// ---------------- edge kernel: attention + scatter-add message ----------------
__global__ void k_edge(const int* __restrict__ sub, const int* __restrict__ rel,
                       const int* __restrict__ ridx, const int* __restrict__ obj,
                       const float* __restrict__ emb, const float* __restrict__ wal,
                       const float* __restrict__ walb) {
    int gt = blockIdx.x * blockDim.x + threadIdx.x;
    int e = gt >> 2;
    if (e >= ENUM) return;
    int lq = threadIdx.x & 3;
    int s = sub[e], r = rel[e], q = ridx[e], o = obj[e];

    float part = 0.f;
#pragma unroll
    for (int u = 0; u < 2; u++) {
        int a = lq * 2 + u;
        float t = g_nproj[s * 8 + a] + g_rproj[r * 8 + a] + g_qproj[q * 8 + a];
        part = fmaf(fmaxf(t, 0.f), __ldg(wal + a), part);
    }
    part += __shfl_xor_sync(0xffffffffu, part, 1);
    part += __shfl_xor_sync(0xffffffffu, part, 2);
    float alpha = sigf(part + __ldg(walb));

    const float4* hs4 = (const float4*)(g_state + (size_t)s * 64);
    const float4* hr4 = (const float4*)(emb + (size_t)r * 64);
    float* ap = g_agg + (size_t)o * 64 + lq * 16;
#pragma unroll
    for (int c = 0; c < 4; c++) {
        float4 a4 = hs4[lq * 4 + c];
        float4 b4 = hr4[lq * 4 + c];
        float mx = alpha * (a4.x + b4.x);
        float my = alpha * (a4.y + b4.y);
        float mz = alpha * (a4.z + b4.z);
        float mw = alpha * (a4.w + b4.w);
        asm volatile("red.global.add.v4.f32 [%0], {%1,%2,%3,%4};"
                     :: "l"(ap + c * 4), "f"(mx), "f"(my), "f"(mz), "f"(mw)
                     : "memory");
    }
}

// ---------------- tf32 mma GEMM: C[M,Nout] = A[M,64] @ W[Nout,64]^T -----------
template <int NTW>
__global__ void k_gemm(const float* __restrict__ Ap, const float* __restrict__ Bf,
                       float* __restrict__ Cp, int Nout, int doRelu) {
    __shared__ float As[32][68];
    int t = threadIdx.x;
    int warp = t >> 5, lane = t & 31;
    int wr = warp >> 2, wc = warp & 3;
    int m0 = blockIdx.x * 32;

#pragma unroll
    for (int p = 0; p < 2; p++) {
        int idx = t + p * 256;
        int r = idx >> 4, c4 = idx & 15;
        float4 v = *((const float4*)(Ap + (size_t)(m0 + r) * 64) + c4);
        As[r][c4 * 4 + 0] = __uint_as_float(f2tf(v.x));
        As[r][c4 * 4 + 1] = __uint_as_float(f2tf(v.y));
        As[r][c4 * 4 + 2] = __uint_as_float(f2tf(v.z));
        As[r][c4 * 4 + 3] = __uint_as_float(f2tf(v.w));
    }
    __syncthreads();

    float acc[NTW][4];
#pragma unroll
    for (int nt = 0; nt < NTW; nt++)
#pragma unroll
        for (int j = 0; j < 4; j++) acc[nt][j] = 0.f;

    int tg = lane >> 2, tig = lane & 3;
    const int NTtot = Nout >> 3;
#pragma unroll
    for (int ks = 0; ks < 8; ks++) {
        int k0 = ks * 8;
        unsigned a0 = __float_as_uint(As[wr * 16 + tg][k0 + tig]);
        unsigned a1 = __float_as_uint(As[wr * 16 + tg + 8][k0 + tig]);
        unsigned a2 = __float_as_uint(As[wr * 16 + tg][k0 + tig + 4]);
        unsigned a3 = __float_as_uint(As[wr * 16 + tg + 8][k0 + tig + 4]);
#pragma unroll
        for (int nt = 0; nt < NTW; nt++) {
            int ntg = wc * NTW + nt;
            float2 b = *(const float2*)(Bf + (((size_t)ks * NTtot + ntg) * 32 + lane) * 2);
            unsigned b0 = __float_as_uint(b.x), b1 = __float_as_uint(b.y);
            asm volatile(
                "mma.sync.aligned.m16n8k8.row.col.f32.tf32.tf32.f32 "
                "{%0,%1,%2,%3}, {%4,%5,%6,%7}, {%8,%9}, {%0,%1,%2,%3};"
                : "+f"(acc[nt][0]), "+f"(acc[nt][1]), "+f"(acc[nt][2]), "+f"(acc[nt][3])
                : "r"(a0), "r"(a1), "r"(a2), "r"(a3), "r"(b0), "r"(b1));
        }
    }

    int row = m0 + wr * 16 + tg;
#pragma unroll
    for (int nt = 0; nt < NTW; nt++) {
        int col = (wc * NTW + nt) * 8 + 2 * tig;
        float v0 = acc[nt][0], v1 = acc[nt][1], v2 = acc[nt][2], v3 = acc[nt][3];
        if (doRelu) {
            v0 = fmaxf(v0, 0.f); v1 = fmaxf(v1, 0.f);
            v2 = fmaxf(v2, 0.f); v3 = fmaxf(v3, 0.f);
        }
        *(float2*)(Cp + (size_t)row * Nout + col) = make_float2(v0, v1);
        *(float2*)(Cp + (size_t)(row + 8) * Nout + col) = make_float2(v2, v3);
    }
}

// ---------------- GRU elementwise update ----------------
__global__ void k_gru(const float* __restrict__ bih, const float* __restrict__ bhh) {
    int i = blockIdx.x * blockDim.x + threadIdx.x;
    if (i >= NNODE * 16) return;
    int n = i >> 4, c = i & 15;
    const float4* gi = (const float4*)(g_GI + (size_t)n * 192);
    const float4* gh = (const float4*)(g_GH + (size_t)n * 192);
    float4* st = (float4*)(g_state + (size_t)n * 64);
    float4 gir = gi[c], giz = gi[16 + c], gin = gi[32 + c];
    float4 ghr = gh[c], ghz = gh[16 + c], ghn = gh[32 + c];
    float4 h = st[c];
    int j = c * 4;
    float4 bir = *(const float4*)(bih + j);
    float4 biz = *(const float4*)(bih + 64 + j);
    float4 bin = *(const float4*)(bih + 128 + j);
    float4 bhr = *(const float4*)(bhh + j);
    float4 bhz = *(const float4*)(bhh + 64 + j);
    float4 bhn = *(const float4*)(bhh + 128 + j);
    float4 out;
#define GRU1(X)                                                          \
    {                                                                    \
        float r = sigf(gir.X + bir.X + ghr.X + bhr.X);                   \
        float z = sigf(giz.X + biz.X + ghz.X + bhz.X);                   \
        float nn = tanhf(gin.X + bin.X + r * (ghn.X + bhn.X));           \
        out.X = (1.f - z) * nn + z * h.X;                                \
    }
    GRU1(x) GRU1(y) GRU1(z) GRU1(w)
#undef GRU1
    st[c] = out;
}

// ---------------- final score + deterministic scatter ----------------
__global__ void k_score(const float* __restrict__ wf, const int* __restrict__ nq,
                        const int* __restrict__ ne) {
    int w = (blockIdx.x * blockDim.x + threadIdx.x) >> 5;
    int lane = threadIdx.x & 31;
    if (w >= NNODE) return;
    float2 s2 = ((const float2*)(g_state + (size_t)w * 64))[lane];
    float2 w2 = __ldg((const float2*)wf + lane);
    float p = s2.x * w2.x + s2.y * w2.y;
#pragma unroll
    for (int m = 16; m >= 1; m >>= 1) p += __shfl_xor_sync(0xffffffffu, p, m);
    if (lane == 0) {
        g_scores[w] = p;
        int slot = nq[w] * ENTC + ne[w];
        atomicMax(&g_winner[slot], w);
    }
}
__global__ void k_scatter(const int* __restrict__ nq, const int* __restrict__ ne,
                          float* __restrict__ out) {
    int n = blockIdx.x * blockDim.x + threadIdx.x;
    if (n >= NNODE) return;
    int slot = nq[n] * ENTC + ne[n];
    if (g_winner[slot] == n) out[slot] = g_scores[n];
}

// ---------------- host launch ----------------
extern "C" void kernel_launch(void* const* d_in, const int* in_sizes, int n_in,
                              void* d_out, int out_size) {
    const int* relation = (const int*)d_in[0];
    const int* r_idx    = (const int*)d_in[1];
    const int* rel      = (const int*)d_in[2];
    const int* sub      = (const int*)d_in[3];
    const int* obj      = (const int*)d_in[4];
    const int* nq       = (const int*)d_in[6];
    const int* ne       = (const int*)d_in[7];
    const float* rela   = (const float*)d_in[8];
    const float* Ws     = (const float*)d_in[9];
    const float* Wr     = (const float*)d_in[10];
    const float* Wqr    = (const float*)d_in[11];
    const float* Wqrb   = (const float*)d_in[12];
    const float* wal    = (const float*)d_in[13];
    const float* walb   = (const float*)d_in[14];
    const float* Wh     = (const float*)d_in[15];
    const float* Wih    = (const float*)d_in[16];
    const float* Whh    = (const float*)d_in[17];
    const float* bih    = (const float*)d_in[18];
    const float* bhh    = (const float*)d_in[19];
    const float* Wfin   = (const float*)d_in[20];
    float* out = (float*)d_out;

    float *p_state, *p_agg, *p_X, *p_GI, *p_GH, *p_bWh, *p_bWih, *p_bWhh;
    int* p_win;
    cudaGetSymbolAddress((void**)&p_state, g_state);
    cudaGetSymbolAddress((void**)&p_agg, g_agg);
    cudaGetSymbolAddress((void**)&p_X, g_X);
    cudaGetSymbolAddress((void**)&p_GI, g_GI);
    cudaGetSymbolAddress((void**)&p_GH, g_GH);
    cudaGetSymbolAddress((void**)&p_bWh, g_bWh);
    cudaGetSymbolAddress((void**)&p_bWih, g_bWih);
    cudaGetSymbolAddress((void**)&p_bWhh, g_bWhh);
    cudaGetSymbolAddress((void**)&p_win, g_winner);

    const int TB = 256;
    // init: state = 0, out = 0, winner = -1
    k_zero4<<<(NNODE * 16 + TB - 1) / TB, TB>>>((float4*)p_state, NNODE * 16);
    k_zero4<<<(QNUM * ENTC / 4 + TB - 1) / TB, TB>>>((float4*)out, QNUM * ENTC / 4);
    k_filli4<<<(QNUM * ENTC / 4 + TB - 1) / TB, TB>>>((int4*)p_win, QNUM * ENTC / 4, -1);
    k_bfrag<<<144, TB>>>(Wh, Wih, Whh);

    for (int i = 0; i < LNUM; i++) {
        const float* emb = rela + (size_t)i * NR2C * DDIM;
        k_zero4<<<(NNODE * 16 + TB - 1) / TB, TB>>>((float4*)p_agg, NNODE * 16);
        {
            int R = NNODE + NR2C + QNUM;
            k_proj<<<(R * 32 + TB - 1) / TB, TB>>>(emb, Ws + i * 512, Wr + i * 512,
                                                   Wqr + i * 512, Wqrb + i * 8, relation);
        }
        k_edge<<<(ENUM * 4 + TB - 1) / TB, TB>>>(sub + (size_t)i * ENUM, rel + (size_t)i * ENUM,
                                                 r_idx + (size_t)i * ENUM, obj + (size_t)i * ENUM,
                                                 emb, wal + i * 8, walb + i);
        k_gemm<2><<<NNODE / 32, TB>>>(p_agg, p_bWh + i * 4096, p_X, 64, 1);
        k_gemm<6><<<NNODE / 32, TB>>>(p_state, p_bWhh, p_GH, 192, 0);
        k_gemm<6><<<NNODE / 32, TB>>>(p_X, p_bWih, p_GI, 192, 0);
        k_gru<<<(NNODE * 16 + TB - 1) / TB, TB>>>(bih, bhh);
    }

    k_score<<<(NNODE * 32 + TB - 1) / TB, TB>>>(Wfin, nq, ne);
    k_scatter<<<(NNODE + TB - 1) / TB, TB>>>(nq, ne, out);
}

// round 3
// speedup vs baseline: 1.3959x; 1.3959x over previous
#include <cuda_runtime.h>

#define LNUM 3
#define ENUM 1000000
#define NNODE 100000
#define DDIM 64
#define ADIM 8
#define NR2C 461
#define QNUM 1000
#define ENTC 10000

// ---------------- scratch (device globals; no allocation) ----------------
__device__ float g_state[NNODE * DDIM];
__device__ float g_agg[NNODE * DDIM];
__device__ float g_nproj[NNODE * ADIM];
__device__ float g_rproj[NR2C * ADIM];
__device__ float g_qproj[QNUM * ADIM];
__device__ float g_bWh[LNUM * 4096];    // per-layer 8ks x 8nt x 32 x 2
__device__ float g_bWih[12288];         // 8ks x 24nt x 32 x 2
__device__ float g_bWhh[12288];
__device__ float g_scores[NNODE];
__device__ int   g_winner[QNUM * ENTC];

// ---------------- helpers ----------------
__device__ __forceinline__ unsigned f2tf(float x) {
    unsigned u;
    asm("cvt.rna.tf32.f32 %0, %1;" : "=r"(u) : "f"(x));
    return u;
}
__device__ __forceinline__ float tf(float x) { return __uint_as_float(f2tf(x)); }
__device__ __forceinline__ float sigf(float x) { return 1.f / (1.f + __expf(-x)); }

__device__ __forceinline__ void mma8(float acc[4], unsigned a0, unsigned a1,
                                     unsigned a2, unsigned a3, unsigned b0, unsigned b1) {
    asm volatile(
        "mma.sync.aligned.m16n8k8.row.col.f32.tf32.tf32.f32 "
        "{%0,%1,%2,%3}, {%4,%5,%6,%7}, {%8,%9}, {%0,%1,%2,%3};"
        : "+f"(acc[0]), "+f"(acc[1]), "+f"(acc[2]), "+f"(acc[3])
        : "r"(a0), "r"(a1), "r"(a2), "r"(a3), "r"(b0), "r"(b1));
}

// ---------------- init kernels ----------------
__global__ void k_zero4(float4* p, int n) {
    int i = blockIdx.x * blockDim.x + threadIdx.x;
    if (i < n) p[i] = make_float4(0.f, 0.f, 0.f, 0.f);
}
__global__ void k_filli4(int4* p, int n, int v) {
    int i = blockIdx.x * blockDim.x + threadIdx.x;
    if (i < n) p[i] = make_int4(v, v, v, v);
}

// ---------------- B-fragment precompute (tf32, mma-swizzled) ----------------
__device__ __forceinline__ float bval(const float* W, int e, int NT) {
    int j = e & 1;
    int lane = (e >> 1) & 31;
    int nk = e >> 6;
    int ntg = nk % NT;
    int ks = nk / NT;
    int n = ntg * 8 + (lane >> 2);
    int k = ks * 8 + (lane & 3) + 4 * j;
    return __uint_as_float(f2tf(W[n * 64 + k]));
}
__global__ void k_bfrag(const float* __restrict__ Wh, const float* __restrict__ Wih,
                        const float* __restrict__ Whh) {
    int i = blockIdx.x * blockDim.x + threadIdx.x;
    const int WH = 4096, WI = 12288;
    if (i < 3 * WH) {
        int layer = i / WH, e = i % WH;
        g_bWh[i] = bval(Wh + layer * 4096, e, 8);
    } else if (i < 3 * WH + WI) {
        int e = i - 3 * WH;
        g_bWih[e] = bval(Wih, e, 24);
    } else if (i < 3 * WH + 2 * WI) {
        int e = i - 3 * WH - WI;
        g_bWhh[e] = bval(Whh, e, 24);
    }
}

// ---------------- per-layer projections: node/rel/query-rel -> 8 attn dims ----
__global__ void k_proj(const float* __restrict__ emb, const float* __restrict__ Ws,
                       const float* __restrict__ Wr, const float* __restrict__ Wqr,
                       const float* __restrict__ Wqrb, const int* __restrict__ relation,
                       int wbase) {
    int w = ((blockIdx.x * blockDim.x + threadIdx.x) >> 5) + wbase;
    int lane = threadIdx.x & 31;
    const int R = NNODE + NR2C + QNUM;
    if (w >= R) return;
    const float* src;
    const float* W;
    float* dst;
    bool isQ = false;
    if (w < NNODE) {
        src = g_state + (size_t)w * 64; W = Ws; dst = g_nproj + w * 8;
    } else if (w < NNODE + NR2C) {
        int r = w - NNODE;
        src = emb + (size_t)r * 64; W = Wr; dst = g_rproj + r * 8;
    } else {
        int q = w - NNODE - NR2C;
        src = emb + (size_t)relation[q] * 64; W = Wqr; dst = g_qproj + q * 8;
        isQ = true;
    }
    float2 s2 = ((const float2*)src)[lane];
    float res = 0.f;
#pragma unroll
    for (int a = 0; a < 8; a++) {
        float2 w2 = __ldg((const float2*)(W + a * 64) + lane);
        float p = s2.x * w2.x + s2.y * w2.y;
#pragma unroll
        for (int m = 16; m >= 1; m >>= 1) p += __shfl_xor_sync(0xffffffffu, p, m);
        if (lane == a) res = p;
    }
    if (lane < 8) dst[lane] = res + (isQ ? Wqrb[lane] : 0.f);
}

// ---------------- edge kernel: attention + scatter-add message ----------------
// HS=false (layer 0): hidden==0 -> skip hs gather and nproj term entirely.
template <bool HS>
__global__ void k_edge(const int* __restrict__ sub, const int* __restrict__ rel,
                       const int* __restrict__ ridx, const int* __restrict__ obj,
                       const float* __restrict__ emb, const float* __restrict__ wal,
                       const float* __restrict__ walb) {
    int gt = blockIdx.x * blockDim.x + threadIdx.x;
    int e = gt >> 2;
    if (e >= ENUM) return;
    int lq = threadIdx.x & 3;
    int r = rel[e], q = ridx[e], o = obj[e];
    int s = HS ? sub[e] : 0;

    float part = 0.f;
#pragma unroll
    for (int u = 0; u < 2; u++) {
        int a = lq * 2 + u;
        float t = g_rproj[r * 8 + a] + g_qproj[q * 8 + a];
        if (HS) t += g_nproj[s * 8 + a];
        part = fmaf(fmaxf(t, 0.f), __ldg(wal + a), part);
    }
    part += __shfl_xor_sync(0xffffffffu, part, 1);
    part += __shfl_xor_sync(0xffffffffu, part, 2);
    float alpha = sigf(part + __ldg(walb));

    const float4* hs4 = (const float4*)(g_state + (size_t)s * 64);
    const float4* hr4 = (const float4*)(emb + (size_t)r * 64);
    float* ap = g_agg + (size_t)o * 64 + lq * 16;
#pragma unroll
    for (int c = 0; c < 4; c++) {
        float4 b4 = hr4[lq * 4 + c];
        float mx, my, mz, mw;
        if (HS) {
            float4 a4 = hs4[lq * 4 + c];
            mx = alpha * (a4.x + b4.x);
            my = alpha * (a4.y + b4.y);
            mz = alpha * (a4.z + b4.z);
            mw = alpha * (a4.w + b4.w);
        } else {
            mx = alpha * b4.x; my = alpha * b4.y;
            mz = alpha * b4.z; mw = alpha * b4.w;
        }
        asm volatile("red.global.add.v4.f32 [%0], {%1,%2,%3,%4};"
                     :: "l"(ap + c * 4), "f"(mx), "f"(my), "f"(mz), "f"(mw)
                     : "memory");
    }
}

// ---------------- fused node phase: X=relu(agg@Wh^T); GRU(X, state) ----------
// 256 threads, 32 rows per block. All GEMMs via tf32 mma; GRU in epilogue.
template <bool FIRST>
__global__ void __launch_bounds__(256, 2)
k_fused(const float* __restrict__ Ap, const float* __restrict__ BWh,
        const float* __restrict__ BWih, const float* __restrict__ BWhh,
        const float* __restrict__ bih, const float* __restrict__ bhh) {
    __shared__ float As[32][68];
    __shared__ float Xs[32][68];
    __shared__ float Ss[32][68];
    int t = threadIdx.x;
    int warp = t >> 5, lane = t & 31;
    int wr = warp >> 2, wc = warp & 3;
    int tg = lane >> 2, tig = lane & 3;
    int m0 = blockIdx.x * 32;

    // load agg tile (and state tile) -> smem as tf32
#pragma unroll
    for (int p = 0; p < 2; p++) {
        int idx = t + p * 256;
        int r = idx >> 4, c4 = idx & 15;
        float4 v = *((const float4*)(Ap + (size_t)(m0 + r) * 64) + c4);
        As[r][c4 * 4 + 0] = tf(v.x);
        As[r][c4 * 4 + 1] = tf(v.y);
        As[r][c4 * 4 + 2] = tf(v.z);
        As[r][c4 * 4 + 3] = tf(v.w);
        if (!FIRST) {
            float4 s = *((const float4*)(g_state + (size_t)(m0 + r) * 64) + c4);
            Ss[r][c4 * 4 + 0] = tf(s.x);
            Ss[r][c4 * 4 + 1] = tf(s.y);
            Ss[r][c4 * 4 + 2] = tf(s.z);
            Ss[r][c4 * 4 + 3] = tf(s.w);
        }
    }
    __syncthreads();

    // --- X = relu(agg @ Wh^T), 64 cols ---
    {
        float accx[2][4] = {};
#pragma unroll
        for (int ks = 0; ks < 8; ks++) {
            int k0 = ks * 8;
            unsigned a0 = __float_as_uint(As[wr * 16 + tg][k0 + tig]);
            unsigned a1 = __float_as_uint(As[wr * 16 + tg + 8][k0 + tig]);
            unsigned a2 = __float_as_uint(As[wr * 16 + tg][k0 + tig + 4]);
            unsigned a3 = __float_as_uint(As[wr * 16 + tg + 8][k0 + tig + 4]);
#pragma unroll
            for (int cg = 0; cg < 2; cg++) {
                int ntg = wc * 2 + cg;
                float2 b = *(const float2*)(BWh + (((size_t)ks * 8 + ntg) * 32 + lane) * 2);
                mma8(accx[cg], a0, a1, a2, a3, __float_as_uint(b.x), __float_as_uint(b.y));
            }
        }
        __syncthreads();  // done reading As before Xs overlaps usage pattern
        int rl = wr * 16 + tg;
#pragma unroll
        for (int cg = 0; cg < 2; cg++) {
            int col = (wc * 2 + cg) * 8 + 2 * tig;
            Xs[rl][col]         = tf(fmaxf(accx[cg][0], 0.f));
            Xs[rl][col + 1]     = tf(fmaxf(accx[cg][1], 0.f));
            Xs[rl + 8][col]     = tf(fmaxf(accx[cg][2], 0.f));
            Xs[rl + 8][col + 1] = tf(fmaxf(accx[cg][3], 0.f));
        }
        __syncthreads();
    }

    // --- gates: r,z accumulate GI+GH together; n keeps GI/GH separate ---
    float acc_r[2][4] = {}, acc_z[2][4] = {}, acc_ni[2][4] = {}, acc_nh[2][4] = {};
#pragma unroll
    for (int ks = 0; ks < 8; ks++) {
        int k0 = ks * 8;
        unsigned x0 = __float_as_uint(Xs[wr * 16 + tg][k0 + tig]);
        unsigned x1 = __float_as_uint(Xs[wr * 16 + tg + 8][k0 + tig]);
        unsigned x2 = __float_as_uint(Xs[wr * 16 + tg][k0 + tig + 4]);
        unsigned x3 = __float_as_uint(Xs[wr * 16 + tg + 8][k0 + tig + 4]);
        unsigned s0 = 0, s1 = 0, s2 = 0, s3 = 0;
        if (!FIRST) {
            s0 = __float_as_uint(Ss[wr * 16 + tg][k0 + tig]);
            s1 = __float_as_uint(Ss[wr * 16 + tg + 8][k0 + tig]);
            s2 = __float_as_uint(Ss[wr * 16 + tg][k0 + tig + 4]);
            s3 = __float_as_uint(Ss[wr * 16 + tg + 8][k0 + tig + 4]);
        }
#pragma unroll
        for (int cg = 0; cg < 2; cg++) {
            int nb = wc * 2 + cg;
#pragma unroll
            for (int g = 0; g < 3; g++) {
                int ntg = g * 8 + nb;
                float2 bi = *(const float2*)(BWih + (((size_t)ks * 24 + ntg) * 32 + lane) * 2);
                float* acc = (g == 0) ? acc_r[cg] : (g == 1) ? acc_z[cg] : acc_ni[cg];
                mma8(acc, x0, x1, x2, x3, __float_as_uint(bi.x), __float_as_uint(bi.y));
                if (!FIRST) {
                    float2 bh = *(const float2*)(BWhh + (((size_t)ks * 24 + ntg) * 32 + lane) * 2);
                    float* acch = (g == 0) ? acc_r[cg] : (g == 1) ? acc_z[cg] : acc_nh[cg];
                    mma8(acch, s0, s1, s2, s3, __float_as_uint(bh.x), __float_as_uint(bh.y));
                }
            }
        }
    }

    // --- GRU epilogue ---
    int r0 = m0 + wr * 16 + tg;
#pragma unroll
    for (int cg = 0; cg < 2; cg++) {
        int col = (wc * 2 + cg) * 8 + 2 * tig;
        float2 bi_r = __ldg((const float2*)(bih + col));
        float2 bh_r = __ldg((const float2*)(bhh + col));
        float2 bi_z = __ldg((const float2*)(bih + 64 + col));
        float2 bh_z = __ldg((const float2*)(bhh + 64 + col));
        float2 bi_n = __ldg((const float2*)(bih + 128 + col));
        float2 bh_n = __ldg((const float2*)(bhh + 128 + col));
        float2 h0v = make_float2(0.f, 0.f), h1v = make_float2(0.f, 0.f);
        if (!FIRST) {
            h0v = *(const float2*)(g_state + (size_t)r0 * 64 + col);
            h1v = *(const float2*)(g_state + (size_t)(r0 + 8) * 64 + col);
        }
#define GRU1(ai, bx, hy, outv)                                                  \
        {                                                                       \
            float rr = sigf(acc_r[cg][ai] + bi_r.bx + bh_r.bx);                 \
            float zz = sigf(acc_z[cg][ai] + bi_z.bx + bh_z.bx);                 \
            float nn = tanhf(acc_ni[cg][ai] + bi_n.bx +                         \
                             rr * (acc_nh[cg][ai] + bh_n.bx));                  \
            outv = (1.f - zz) * nn + zz * hy;                                   \
        }
        float2 o0, o1;
        GRU1(0, x, h0v.x, o0.x)
        GRU1(1, y, h0v.y, o0.y)
        GRU1(2, x, h1v.x, o1.x)
        GRU1(3, y, h1v.y, o1.y)
#undef GRU1
        *(float2*)(g_state + (size_t)r0 * 64 + col) = o0;
        *(float2*)(g_state + (size_t)(r0 + 8) * 64 + col) = o1;
    }
}

// ---------------- final score + deterministic scatter ----------------
__global__ void k_score(const float* __restrict__ wf, const int* __restrict__ nq,
                        const int* __restrict__ ne) {
    int w = (blockIdx.x * blockDim.x + threadIdx.x) >> 5;
    int lane = threadIdx.x & 31;
    if (w >= NNODE) return;
    float2 s2 = ((const float2*)(g_state + (size_t)w * 64))[lane];
    float2 w2 = __ldg((const float2*)wf + lane);
    float p = s2.x * w2.x + s2.y * w2.y;
#pragma unroll
    for (int m = 16; m >= 1; m >>= 1) p += __shfl_xor_sync(0xffffffffu, p, m);
    if (lane == 0) {
        g_scores[w] = p;
        int slot = nq[w] * ENTC + ne[w];
        atomicMax(&g_winner[slot], w);
    }
}
__global__ void k_scatter(const int* __restrict__ nq, const int* __restrict__ ne,
                          float* __restrict__ out) {
    int n = blockIdx.x * blockDim.x + threadIdx.x;
    if (n >= NNODE) return;
    int slot = nq[n] * ENTC + ne[n];
    if (g_winner[slot] == n) out[slot] = g_scores[n];
}

// ---------------- host launch ----------------
extern "C" void kernel_launch(void* const* d_in, const int* in_sizes, int n_in,
                              void* d_out, int out_size) {
    const int* relation = (const int*)d_in[0];
    const int* r_idx    = (const int*)d_in[1];
    const int* rel      = (const int*)d_in[2];
    const int* sub      = (const int*)d_in[3];
    const int* obj      = (const int*)d_in[4];
    const int* nq       = (const int*)d_in[6];
    const int* ne       = (const int*)d_in[7];
    const float* rela   = (const float*)d_in[8];
    const float* Ws     = (const float*)d_in[9];
    const float* Wr     = (const float*)d_in[10];
    const float* Wqr    = (const float*)d_in[11];
    const float* Wqrb   = (const float*)d_in[12];
    const float* wal    = (const float*)d_in[13];
    const float* walb   = (const float*)d_in[14];
    const float* Wh     = (const float*)d_in[15];
    const float* Wih    = (const float*)d_in[16];
    const float* Whh    = (const float*)d_in[17];
    const float* bih    = (const float*)d_in[18];
    const float* bhh    = (const float*)d_in[19];
    const float* Wfin   = (const float*)d_in[20];
    float* out = (float*)d_out;

    float *p_state, *p_agg, *p_bWh, *p_bWih, *p_bWhh;
    int* p_win;
    cudaGetSymbolAddress((void**)&p_state, g_state);
    cudaGetSymbolAddress((void**)&p_agg, g_agg);
    cudaGetSymbolAddress((void**)&p_bWh, g_bWh);
    cudaGetSymbolAddress((void**)&p_bWih, g_bWih);
    cudaGetSymbolAddress((void**)&p_bWhh, g_bWhh);
    cudaGetSymbolAddress((void**)&p_win, g_winner);

    const int TB = 256;
    k_zero4<<<(NNODE * 16 + TB - 1) / TB, TB>>>((float4*)p_state, NNODE * 16);
    k_zero4<<<(QNUM * ENTC / 4 + TB - 1) / TB, TB>>>((float4*)out, QNUM * ENTC / 4);
    k_filli4<<<(QNUM * ENTC / 4 + TB - 1) / TB, TB>>>((int4*)p_win, QNUM * ENTC / 4, -1);
    k_bfrag<<<144, TB>>>(Wh, Wih, Whh);

    for (int i = 0; i < LNUM; i++) {
        const float* emb = rela + (size_t)i * NR2C * DDIM;
        k_zero4<<<(NNODE * 16 + TB - 1) / TB, TB>>>((float4*)p_agg, NNODE * 16);
        if (i == 0) {
            int R = NR2C + QNUM;
            k_proj<<<(R * 32 + TB - 1) / TB, TB>>>(emb, Ws + i * 512, Wr + i * 512,
                                                   Wqr + i * 512, Wqrb + i * 8, relation,
                                                   NNODE);
            k_edge<false><<<(ENUM * 4 + TB - 1) / TB, TB>>>(
                sub + (size_t)i * ENUM, rel + (size_t)i * ENUM, r_idx + (size_t)i * ENUM,
                obj + (size_t)i * ENUM, emb, wal + i * 8, walb + i);
            k_fused<true><<<NNODE / 32, TB>>>(p_agg, p_bWh + i * 4096, p_bWih, p_bWhh,
                                              bih, bhh);
        } else {
            int R = NNODE + NR2C + QNUM;
            k_proj<<<(R * 32 + TB - 1) / TB, TB>>>(emb, Ws + i * 512, Wr + i * 512,
                                                   Wqr + i * 512, Wqrb + i * 8, relation, 0);
            k_edge<true><<<(ENUM * 4 + TB - 1) / TB, TB>>>(
                sub + (size_t)i * ENUM, rel + (size_t)i * ENUM, r_idx + (size_t)i * ENUM,
                obj + (size_t)i * ENUM, emb, wal + i * 8, walb + i);
            k_fused<false><<<NNODE / 32, TB>>>(p_agg, p_bWh + i * 4096, p_bWih, p_bWhh,
                                               bih, bhh);
        }
    }

    k_score<<<(NNODE * 32 + TB - 1) / TB, TB>>>(Wfin, nq, ne);
    k_scatter<<<(NNODE + TB - 1) / TB, TB>>>(nq, ne, out);
}